// round 2
// baseline (speedup 1.0000x reference)
#include <cuda_runtime.h>

// Problem-shape constants (fixed for this dataset)
#define NMAX  65536
#define C1    128
#define C2    256
#define CIN   384   // C1 + C2
#define COUT  256
#define NN_TILE 1024
#define STAT_BLKS 256

// ---------------- scratch (device globals; no allocation allowed) ----------
__device__ float g_w[NMAX * 3];        // interpolation weights
__device__ int   g_i[NMAX * 3];        // 3-NN global indices
__device__ float g_X[NMAX * CIN];      // X (N x 384), reused as X2 (N x 256)
__device__ float g_H[NMAX * COUT];     // GEMM output (H1 then H2)
__device__ float g_psum[STAT_BLKS * COUT];
__device__ float g_psq [STAT_BLKS * COUT];
__device__ float g_scale[COUT];
__device__ float g_shift[COUT];

// ---------------- 1) ragged brute-force 3-NN -------------------------------
__global__ void three_nn_kernel(const float* __restrict__ unknown,
                                const int*   __restrict__ ub_cnt,
                                const float* __restrict__ known,
                                const int*   __restrict__ kb_cnt,
                                int N, int B)
{
    __shared__ float skx[NN_TILE], sky[NN_TILE], skz[NN_TILE];

    int n = blockIdx.x * blockDim.x + threadIdx.x;
    float ux = 0.f, uy = 0.f, uz = 0.f;
    int myb = -1;
    if (n < N) {
        ux = unknown[n * 3 + 0];
        uy = unknown[n * 3 + 1];
        uz = unknown[n * 3 + 2];
        int acc = 0;
        for (int b = 0; b < B; b++) {
            acc += ub_cnt[b];
            if (n < acc) { myb = b; break; }
        }
    }

    const float INF = __int_as_float(0x7f800000);
    float d0 = INF, d1 = INF, d2v = INF;
    int   i0 = 0,  i1 = 0,  i2 = 0;

    int kacc = 0;
    for (int b = 0; b < B; b++) {
        int ks = kacc;
        kacc += kb_cnt[b];
        int ke = kacc;
        for (int t = ks; t < ke; t += NN_TILE) {
            int cnt = min(NN_TILE, ke - t);
            __syncthreads();
            for (int i = threadIdx.x; i < cnt; i += blockDim.x) {
                skx[i] = known[(t + i) * 3 + 0];
                sky[i] = known[(t + i) * 3 + 1];
                skz[i] = known[(t + i) * 3 + 2];
            }
            __syncthreads();
            if (myb == b) {
#pragma unroll 4
                for (int j = 0; j < cnt; j++) {
                    float dx = ux - skx[j];
                    float dy = uy - sky[j];
                    float dz = uz - skz[j];
                    float d = dx * dx + dy * dy + dz * dz;
                    if (d < d2v) {
                        int gi = t + j;
                        if (d < d1) {
                            d2v = d1; i2 = i1;
                            if (d < d0) { d1 = d0; i1 = i0; d0 = d; i0 = gi; }
                            else        { d1 = d;  i1 = gi; }
                        } else { d2v = d; i2 = gi; }
                    }
                }
            }
        }
    }

    if (n < N) {
        float r0 = 1.f / (d0  + 1e-8f);
        float r1 = 1.f / (d1  + 1e-8f);
        float r2 = 1.f / (d2v + 1e-8f);
        float s  = 1.f / (r0 + r1 + r2);
        g_w[n * 3 + 0] = r0 * s;
        g_w[n * 3 + 1] = r1 * s;
        g_w[n * 3 + 2] = r2 * s;
        g_i[n * 3 + 0] = i0;
        g_i[n * 3 + 1] = i1;
        g_i[n * 3 + 2] = i2;
    }
}

// ---------------- 2) interpolate + concat into X ----------------------------
__global__ void gather_interp(const float* __restrict__ kf, int N)
{
    int n = blockIdx.x;          // one block (256 threads) per point
    int c = threadIdx.x;
    float w0 = g_w[n * 3 + 0], w1 = g_w[n * 3 + 1], w2 = g_w[n * 3 + 2];
    int   i0 = g_i[n * 3 + 0], i1 = g_i[n * 3 + 1], i2 = g_i[n * 3 + 2];
    float v = w0 * kf[(size_t)i0 * C2 + c]
            + w1 * kf[(size_t)i1 * C2 + c]
            + w2 * kf[(size_t)i2 * C2 + c];
    g_X[(size_t)n * CIN + c] = v;
}

__global__ void copy_feats(const float* __restrict__ uf, int N)
{
    int tid = blockIdx.x * blockDim.x + threadIdx.x;
    if (tid < N * C1) {
        int n = tid >> 7;        // /C1
        int c = tid & (C1 - 1);
        g_X[(size_t)n * CIN + C2 + c] = uf[tid];
    }
}

// ---------------- 3) SGEMM: g_H = g_X(:, :K) @ W^T --------------------------
// C[m, n] = sum_k A[m,k] * W[n,k];  A row stride = K, 128x128x8 tiles,
// 256 threads, 8x8 register micro-tile per thread.
template <int K>
__global__ __launch_bounds__(256) void sgemm(const float* __restrict__ W, int Mrows)
{
    __shared__ float As[8][128];
    __shared__ float Bs[8][128];

    const int tid = threadIdx.x;
    const int tx = tid & 15;          // 16 threads along N
    const int ty = tid >> 4;          // 16 threads along M
    const float* A  = g_X + (size_t)blockIdx.y * 128 * K;
    const float* Wb = W   + (size_t)blockIdx.x * 128 * K;

    const int ar = tid >> 1;          // row (0..127) to load
    const int kq = (tid & 1) * 4;     // which float4 within the 8-wide k slice

    float acc[8][8];
#pragma unroll
    for (int i = 0; i < 8; i++)
#pragma unroll
        for (int j = 0; j < 8; j++) acc[i][j] = 0.f;

    for (int kt = 0; kt < K; kt += 8) {
        float4 av = *(const float4*)(A  + (size_t)ar * K + kt + kq);
        float4 wv = *(const float4*)(Wb + (size_t)ar * K + kt + kq);
        __syncthreads();
        As[kq + 0][ar] = av.x; As[kq + 1][ar] = av.y;
        As[kq + 2][ar] = av.z; As[kq + 3][ar] = av.w;
        Bs[kq + 0][ar] = wv.x; Bs[kq + 1][ar] = wv.y;
        Bs[kq + 2][ar] = wv.z; Bs[kq + 3][ar] = wv.w;
        __syncthreads();
#pragma unroll
        for (int k = 0; k < 8; k++) {
            float4 a0 = *(const float4*)&As[k][ty * 8];
            float4 a1 = *(const float4*)&As[k][ty * 8 + 4];
            float4 b0 = *(const float4*)&Bs[k][tx * 8];
            float4 b1 = *(const float4*)&Bs[k][tx * 8 + 4];
            float ra[8] = {a0.x, a0.y, a0.z, a0.w, a1.x, a1.y, a1.z, a1.w};
            float rb[8] = {b0.x, b0.y, b0.z, b0.w, b1.x, b1.y, b1.z, b1.w};
#pragma unroll
            for (int i = 0; i < 8; i++)
#pragma unroll
                for (int j = 0; j < 8; j++)
                    acc[i][j] = fmaf(ra[i], rb[j], acc[i][j]);
        }
    }

    float* Cp = g_H + ((size_t)blockIdx.y * 128 + ty * 8) * COUT
                    + blockIdx.x * 128 + tx * 8;
#pragma unroll
    for (int i = 0; i < 8; i++) {
        *(float4*)(Cp + (size_t)i * COUT)     = make_float4(acc[i][0], acc[i][1], acc[i][2], acc[i][3]);
        *(float4*)(Cp + (size_t)i * COUT + 4) = make_float4(acc[i][4], acc[i][5], acc[i][6], acc[i][7]);
    }
}

// ---------------- 4) BN column stats (deterministic 2-stage) -----------------
__global__ void col_stats(int N)
{
    int c = threadIdx.x;                       // 256 cols
    int rows = N / gridDim.x;
    int r0 = blockIdx.x * rows;
    float s = 0.f, sq = 0.f;
    for (int r = r0; r < r0 + rows; r++) {
        float v = g_H[(size_t)r * COUT + c];
        s += v;
        sq = fmaf(v, v, sq);
    }
    g_psum[blockIdx.x * COUT + c] = s;
    g_psq [blockIdx.x * COUT + c] = sq;
}

__global__ void finalize_stats(const float* __restrict__ gamma,
                               const float* __restrict__ beta,
                               int N, int nblk)
{
    int c = threadIdx.x;
    double s = 0.0, sq = 0.0;
    for (int b = 0; b < nblk; b++) {
        s  += (double)g_psum[b * COUT + c];
        sq += (double)g_psq [b * COUT + c];
    }
    double mean = s / (double)N;
    double var  = sq / (double)N - mean * mean;
    float  sc   = gamma[c] * rsqrtf((float)var + 1e-5f);
    g_scale[c] = sc;
    g_shift[c] = beta[c] - (float)mean * sc;
}

// ---------------- 5) BN apply + ReLU ----------------------------------------
__global__ void bn_relu_to_X(long total)
{
    long tid = (long)blockIdx.x * blockDim.x + threadIdx.x;
    if (tid < total) {
        int c = (int)(tid & (COUT - 1));
        float v = fmaf(g_H[tid], g_scale[c], g_shift[c]);
        g_X[tid] = fmaxf(v, 0.f);   // X region reused as the 256-wide X2
    }
}

__global__ void bn_relu_to_out(float* __restrict__ out, long total)
{
    long tid = (long)blockIdx.x * blockDim.x + threadIdx.x;
    if (tid < total) {
        int c = (int)(tid & (COUT - 1));
        float v = fmaf(g_H[tid], g_scale[c], g_shift[c]);
        out[tid] = fmaxf(v, 0.f);
    }
}

// ---------------- launch -----------------------------------------------------
extern "C" void kernel_launch(void* const* d_in, const int* in_sizes, int n_in,
                              void* d_out, int out_size)
{
    const float* unknown = (const float*)d_in[0];
    const int*   ub_cnt  = (const int*)  d_in[1];
    const float* known   = (const float*)d_in[2];
    const int*   kb_cnt  = (const int*)  d_in[3];
    const float* uf      = (const float*)d_in[4];
    const float* kf      = (const float*)d_in[5];
    const float* W1      = (const float*)d_in[6];
    const float* g1      = (const float*)d_in[7];
    const float* b1      = (const float*)d_in[8];
    const float* W2      = (const float*)d_in[9];
    const float* g2      = (const float*)d_in[10];
    const float* b2      = (const float*)d_in[11];
    float* out = (float*)d_out;

    int N = in_sizes[0] / 3;
    int B = in_sizes[1];
    long totalH = (long)N * COUT;

    three_nn_kernel<<<(N + 255) / 256, 256>>>(unknown, ub_cnt, known, kb_cnt, N, B);
    gather_interp<<<N, C2>>>(kf, N);
    copy_feats<<<(N * C1 + 255) / 256, 256>>>(uf, N);

    sgemm<CIN><<<dim3(COUT / 128, N / 128), 256>>>(W1, N);
    col_stats<<<STAT_BLKS, COUT>>>(N);
    finalize_stats<<<1, COUT>>>(g1, b1, N, STAT_BLKS);
    bn_relu_to_X<<<(int)((totalH + 255) / 256), 256>>>(totalH);

    sgemm<COUT><<<dim3(COUT / 128, N / 128), 256>>>(W2, N);
    col_stats<<<STAT_BLKS, COUT>>>(N);
    finalize_stats<<<1, COUT>>>(g2, b2, N, STAT_BLKS);
    bn_relu_to_out<<<(int)((totalH + 255) / 256), 256>>>(out, totalH);
}

// round 5
// speedup vs baseline: 1.0718x; 1.0718x over previous
#include <cuda_runtime.h>
#include <cstdint>

// Problem-shape constants (fixed for this dataset)
#define NMAX  65536
#define C1    128
#define C2    256
#define COUT  256
#define NN_TILE 1024
#define STAT_BLKS 256

// ---------------- scratch (device globals; no allocation allowed) ----------
__device__ float g_w[NMAX * 3];        // interpolation weights
__device__ int   g_i[NMAX * 3];        // 3-NN global indices
__device__ float g_H [NMAX * COUT];    // layer-1 pre-BN output
__device__ float g_H2[NMAX * COUT];    // layer-2 pre-BN output
__device__ float g_psum[STAT_BLKS * COUT];
__device__ float g_psq [STAT_BLKS * COUT];
__device__ float g_scale[COUT];
__device__ float g_shift[COUT];

// ---------------- 1) ragged brute-force 3-NN (2 pts/thread, score trick) ----
// rank by t = u.k - 0.5|k|^2 (max), identical ordering to squared distance.
__global__ __launch_bounds__(256) void three_nn_kernel(
    const float* __restrict__ unknown,
    const int*   __restrict__ ub_cnt,
    const float* __restrict__ known,
    const int*   __restrict__ kb_cnt,
    int N, int B)
{
    __shared__ float4 sk[NN_TILE];

    const int tid  = threadIdx.x;
    const int base = blockIdx.x * 512;           // 256 threads x 2 points
    const int n0 = base + tid;
    const int n1 = base + 256 + tid;

    float ux0 = 0.f, uy0 = 0.f, uz0 = 0.f;
    float ux1 = 0.f, uy1 = 0.f, uz1 = 0.f;
    int b0i = -1, b1i = -1;
    if (n0 < N) { ux0 = unknown[n0*3]; uy0 = unknown[n0*3+1]; uz0 = unknown[n0*3+2]; }
    if (n1 < N) { ux1 = unknown[n1*3]; uy1 = unknown[n1*3+1]; uz1 = unknown[n1*3+2]; }
    {
        int acc = 0;
        for (int b = 0; b < B; b++) {
            int nx = acc + ub_cnt[b];
            if (n0 < N && n0 >= acc && n0 < nx) b0i = b;
            if (n1 < N && n1 >= acc && n1 < nx) b1i = b;
            acc = nx;
        }
    }

    const float NEG = -__int_as_float(0x7f800000);
    float s00 = NEG, s01 = NEG, s02 = NEG;   // point 0: best..3rd scores (desc)
    float s10 = NEG, s11 = NEG, s12 = NEG;   // point 1
    int   a00 = 0, a01 = 0, a02 = 0;
    int   a10 = 0, a11 = 0, a12 = 0;

    int kacc = 0;
    for (int b = 0; b < B; b++) {
        int ks = kacc;
        kacc += kb_cnt[b];
        int ke = kacc;
        bool act0 = (b0i == b), act1 = (b1i == b);
        int any = __syncthreads_or((int)(act0 || act1));
        if (!any) continue;

        for (int t = ks; t < ke; t += NN_TILE) {
            int cnt = min(NN_TILE, ke - t);
            __syncthreads();
            for (int i = tid; i < cnt; i += 256) {
                float kx = known[(t + i) * 3 + 0];
                float ky = known[(t + i) * 3 + 1];
                float kz = known[(t + i) * 3 + 2];
                float h  = 0.5f * (kx * kx + ky * ky + kz * kz);
                sk[i] = make_float4(kx, ky, kz, h);
            }
            __syncthreads();

            if (act0 && act1) {
#pragma unroll 4
                for (int j = 0; j < cnt; j++) {
                    float4 kk = sk[j];
                    int gi = t + j;
                    float t0 = fmaf(ux0, kk.x, fmaf(uy0, kk.y, fmaf(uz0, kk.z, -kk.w)));
                    float t1 = fmaf(ux1, kk.x, fmaf(uy1, kk.y, fmaf(uz1, kk.z, -kk.w)));
                    if (t0 > s02) {
                        if (t0 > s01) {
                            s02 = s01; a02 = a01;
                            if (t0 > s00) { s01 = s00; a01 = a00; s00 = t0; a00 = gi; }
                            else          { s01 = t0;  a01 = gi; }
                        } else { s02 = t0; a02 = gi; }
                    }
                    if (t1 > s12) {
                        if (t1 > s11) {
                            s12 = s11; a12 = a11;
                            if (t1 > s10) { s11 = s10; a11 = a10; s10 = t1; a10 = gi; }
                            else          { s11 = t1;  a11 = gi; }
                        } else { s12 = t1; a12 = gi; }
                    }
                }
            } else if (act0) {
#pragma unroll 4
                for (int j = 0; j < cnt; j++) {
                    float4 kk = sk[j];
                    int gi = t + j;
                    float t0 = fmaf(ux0, kk.x, fmaf(uy0, kk.y, fmaf(uz0, kk.z, -kk.w)));
                    if (t0 > s02) {
                        if (t0 > s01) {
                            s02 = s01; a02 = a01;
                            if (t0 > s00) { s01 = s00; a01 = a00; s00 = t0; a00 = gi; }
                            else          { s01 = t0;  a01 = gi; }
                        } else { s02 = t0; a02 = gi; }
                    }
                }
            } else if (act1) {
#pragma unroll 4
                for (int j = 0; j < cnt; j++) {
                    float4 kk = sk[j];
                    int gi = t + j;
                    float t1 = fmaf(ux1, kk.x, fmaf(uy1, kk.y, fmaf(uz1, kk.z, -kk.w)));
                    if (t1 > s12) {
                        if (t1 > s11) {
                            s12 = s11; a12 = a11;
                            if (t1 > s10) { s11 = s10; a11 = a10; s10 = t1; a10 = gi; }
                            else          { s11 = t1;  a11 = gi; }
                        } else { s12 = t1; a12 = gi; }
                    }
                }
            }
        }
    }

    // exact squared distances for the winners -> weights (same formula as before)
    if (n0 < N) {
        float d[3]; int ai[3] = {a00, a01, a02};
#pragma unroll
        for (int q = 0; q < 3; q++) {
            float dx = ux0 - known[ai[q]*3], dy = uy0 - known[ai[q]*3+1], dz = uz0 - known[ai[q]*3+2];
            d[q] = dx*dx + dy*dy + dz*dz;
        }
        float r0 = 1.f/(d[0]+1e-8f), r1 = 1.f/(d[1]+1e-8f), r2 = 1.f/(d[2]+1e-8f);
        float s = 1.f/(r0+r1+r2);
        g_w[n0*3+0] = r0*s; g_w[n0*3+1] = r1*s; g_w[n0*3+2] = r2*s;
        g_i[n0*3+0] = ai[0]; g_i[n0*3+1] = ai[1]; g_i[n0*3+2] = ai[2];
    }
    if (n1 < N) {
        float d[3]; int ai[3] = {a10, a11, a12};
#pragma unroll
        for (int q = 0; q < 3; q++) {
            float dx = ux1 - known[ai[q]*3], dy = uy1 - known[ai[q]*3+1], dz = uz1 - known[ai[q]*3+2];
            d[q] = dx*dx + dy*dy + dz*dz;
        }
        float r0 = 1.f/(d[0]+1e-8f), r1 = 1.f/(d[1]+1e-8f), r2 = 1.f/(d[2]+1e-8f);
        float s = 1.f/(r0+r1+r2);
        g_w[n1*3+0] = r0*s; g_w[n1*3+1] = r1*s; g_w[n1*3+2] = r2*s;
        g_i[n1*3+0] = ai[0]; g_i[n1*3+1] = ai[1]; g_i[n1*3+2] = ai[2];
    }
}

// ---------------- 2) fused double-buffered fp32 SGEMM ----------------------
// C[m,o] = sum_k A[m,k] * W[o,k]; 128x128 tile, 256 thr, 8x8 microtile.
// MODE 0: A built on the fly = [interp(kf, w, i) | uf]   (K = 384)
// MODE 1: A = relu(bn(Asrc)) with g_scale/g_shift          (K = 256)
template <int K, int MODE>
__global__ __launch_bounds__(256) void gemm_fused(
    const float* __restrict__ Asrc,
    const float* __restrict__ kf,
    const float* __restrict__ uf,
    const float* __restrict__ W,
    float* __restrict__ Cdst)
{
    __shared__ float As[2][8][128];
    __shared__ float Bs[2][8][128];
    __shared__ float ssc[256], ssh[256];

    const int tid = threadIdx.x;
    const int tx = tid & 15;          // 16 threads along N
    const int ty = tid >> 4;          // 16 threads along M
    const int ar = tid >> 1;          // row 0..127 loaded by this thread
    const int kq = (tid & 1) * 4;     // float4 within 8-wide k slice
    const int row0 = blockIdx.y * 128;
    const float* Wb = W + (size_t)blockIdx.x * 128 * K;

    if (MODE == 1) { ssc[tid] = g_scale[tid]; ssh[tid] = g_shift[tid]; }

    // per-thread A row is fixed: preload interpolation weights/indices once
    const int n = row0 + ar;
    float w0 = 0.f, w1 = 0.f, w2 = 0.f;
    int   j0 = 0,   j1 = 0,   j2 = 0;
    if (MODE == 0) {
        w0 = g_w[n*3+0]; w1 = g_w[n*3+1]; w2 = g_w[n*3+2];
        j0 = g_i[n*3+0]; j1 = g_i[n*3+1]; j2 = g_i[n*3+2];
    }
    if (MODE == 1) __syncthreads();   // ssc/ssh visible

    auto loadA = [&](int kt) -> float4 {
        int k0 = kt + kq;
        float4 v;
        if (MODE == 0) {
            if (k0 < C2) {
                float4 a = *(const float4*)(kf + (size_t)j0 * C2 + k0);
                float4 b = *(const float4*)(kf + (size_t)j1 * C2 + k0);
                float4 e = *(const float4*)(kf + (size_t)j2 * C2 + k0);
                v.x = w0*a.x + w1*b.x + w2*e.x;
                v.y = w0*a.y + w1*b.y + w2*e.y;
                v.z = w0*a.z + w1*b.z + w2*e.z;
                v.w = w0*a.w + w1*b.w + w2*e.w;
            } else {
                v = *(const float4*)(uf + (size_t)n * C1 + (k0 - C2));
            }
        } else {
            v = *(const float4*)(Asrc + (size_t)n * COUT + k0);
            v.x = fmaxf(fmaf(v.x, ssc[k0+0], ssh[k0+0]), 0.f);
            v.y = fmaxf(fmaf(v.y, ssc[k0+1], ssh[k0+1]), 0.f);
            v.z = fmaxf(fmaf(v.z, ssc[k0+2], ssh[k0+2]), 0.f);
            v.w = fmaxf(fmaf(v.w, ssc[k0+3], ssh[k0+3]), 0.f);
        }
        return v;
    };

    float acc[8][8];
#pragma unroll
    for (int i = 0; i < 8; i++)
#pragma unroll
        for (int j = 0; j < 8; j++) acc[i][j] = 0.f;

    // prologue: fill buffer 0
    {
        float4 av = loadA(0);
        float4 wv = *(const float4*)(Wb + (size_t)ar * K + kq);
        As[0][kq+0][ar] = av.x; As[0][kq+1][ar] = av.y;
        As[0][kq+2][ar] = av.z; As[0][kq+3][ar] = av.w;
        Bs[0][kq+0][ar] = wv.x; Bs[0][kq+1][ar] = wv.y;
        Bs[0][kq+2][ar] = wv.z; Bs[0][kq+3][ar] = wv.w;
    }
    __syncthreads();

    const int NK = K / 8;
    for (int kt = 0; kt < NK; kt++) {
        const int buf = kt & 1;
        float4 av, wv;
        if (kt + 1 < NK) {
            av = loadA((kt + 1) * 8);
            wv = *(const float4*)(Wb + (size_t)ar * K + (kt + 1) * 8 + kq);
        }
#pragma unroll
        for (int k = 0; k < 8; k++) {
            float4 a0 = *(const float4*)&As[buf][k][ty * 8];
            float4 a1 = *(const float4*)&As[buf][k][ty * 8 + 4];
            float4 b0 = *(const float4*)&Bs[buf][k][tx * 4];        // cols tx*4..+3
            float4 b1 = *(const float4*)&Bs[buf][k][64 + tx * 4];   // cols 64+tx*4..+3
            float ra[8] = {a0.x, a0.y, a0.z, a0.w, a1.x, a1.y, a1.z, a1.w};
            float rb[8] = {b0.x, b0.y, b0.z, b0.w, b1.x, b1.y, b1.z, b1.w};
#pragma unroll
            for (int i = 0; i < 8; i++)
#pragma unroll
                for (int j = 0; j < 8; j++)
                    acc[i][j] = fmaf(ra[i], rb[j], acc[i][j]);
        }
        if (kt + 1 < NK) {
            const int nb = buf ^ 1;
            As[nb][kq+0][ar] = av.x; As[nb][kq+1][ar] = av.y;
            As[nb][kq+2][ar] = av.z; As[nb][kq+3][ar] = av.w;
            Bs[nb][kq+0][ar] = wv.x; Bs[nb][kq+1][ar] = wv.y;
            Bs[nb][kq+2][ar] = wv.z; Bs[nb][kq+3][ar] = wv.w;
        }
        __syncthreads();
    }

    // epilogue: rows ty*8..+7, cols {bx*128 + tx*4 ..} and {bx*128 + 64 + tx*4 ..}
    float* Cb = Cdst + (size_t)(row0 + ty * 8) * COUT + blockIdx.x * 128;
#pragma unroll
    for (int i = 0; i < 8; i++) {
        *(float4*)(Cb + (size_t)i * COUT + tx * 4)      = make_float4(acc[i][0], acc[i][1], acc[i][2], acc[i][3]);
        *(float4*)(Cb + (size_t)i * COUT + 64 + tx * 4) = make_float4(acc[i][4], acc[i][5], acc[i][6], acc[i][7]);
    }
}

// ---------------- 3) BN column stats (deterministic 2-stage) -----------------
__global__ void col_stats(const float* __restrict__ H, int N)
{
    int c = threadIdx.x;                       // 256 cols
    int rows = N / gridDim.x;
    int r0 = blockIdx.x * rows;
    float s = 0.f, sq = 0.f;
    for (int r = r0; r < r0 + rows; r++) {
        float v = H[(size_t)r * COUT + c];
        s += v;
        sq = fmaf(v, v, sq);
    }
    g_psum[blockIdx.x * COUT + c] = s;
    g_psq [blockIdx.x * COUT + c] = sq;
}

__global__ void finalize_stats(const float* __restrict__ gamma,
                               const float* __restrict__ beta,
                               int N, int nblk)
{
    int c = threadIdx.x;
    double s = 0.0, sq = 0.0;
    for (int b = 0; b < nblk; b++) {
        s  += (double)g_psum[b * COUT + c];
        sq += (double)g_psq [b * COUT + c];
    }
    double mean = s / (double)N;
    double var  = sq / (double)N - mean * mean;
    float  sc   = gamma[c] * rsqrtf((float)var + 1e-5f);
    g_scale[c] = sc;
    g_shift[c] = beta[c] - (float)mean * sc;
}

// ---------------- 4) final BN apply + ReLU (vectorized) ----------------------
__global__ void bn_relu_out4(const float4* __restrict__ H, float4* __restrict__ out, int total4)
{
    int t = blockIdx.x * blockDim.x + threadIdx.x;
    if (t < total4) {
        int c = (t & 63) * 4;       // element col = (4t) % 256
        float4 v = H[t];
        v.x = fmaxf(fmaf(v.x, g_scale[c+0], g_shift[c+0]), 0.f);
        v.y = fmaxf(fmaf(v.y, g_scale[c+1], g_shift[c+1]), 0.f);
        v.z = fmaxf(fmaf(v.z, g_scale[c+2], g_shift[c+2]), 0.f);
        v.w = fmaxf(fmaf(v.w, g_scale[c+3], g_shift[c+3]), 0.f);
        out[t] = v;
    }
}

// ---------------- launch -----------------------------------------------------
extern "C" void kernel_launch(void* const* d_in, const int* in_sizes, int n_in,
                              void* d_out, int out_size)
{
    const float* unknown = (const float*)d_in[0];
    const int*   ub_cnt  = (const int*)  d_in[1];
    const float* known   = (const float*)d_in[2];
    const int*   kb_cnt  = (const int*)  d_in[3];
    const float* uf      = (const float*)d_in[4];
    const float* kf      = (const float*)d_in[5];
    const float* W1      = (const float*)d_in[6];
    const float* g1      = (const float*)d_in[7];
    const float* b1      = (const float*)d_in[8];
    const float* W2      = (const float*)d_in[9];
    const float* g2      = (const float*)d_in[10];
    const float* b2      = (const float*)d_in[11];
    float* out = (float*)d_out;

    int N = in_sizes[0] / 3;
    int B = in_sizes[1];
    int total4 = (int)(((long)N * COUT) / 4);

    float* Hp = nullptr; float* H2p = nullptr;
    cudaGetSymbolAddress((void**)&Hp,  g_H);
    cudaGetSymbolAddress((void**)&H2p, g_H2);

    three_nn_kernel<<<(N + 511) / 512, 256>>>(unknown, ub_cnt, known, kb_cnt, N, B);

    gemm_fused<384, 0><<<dim3(2, N / 128), 256>>>(nullptr, kf, uf, W1, Hp);
    col_stats<<<STAT_BLKS, COUT>>>(Hp, N);
    finalize_stats<<<1, COUT>>>(g1, b1, N, STAT_BLKS);

    gemm_fused<256, 1><<<dim3(2, N / 128), 256>>>(Hp, nullptr, nullptr, W2, H2p);
    col_stats<<<STAT_BLKS, COUT>>>(H2p, N);
    finalize_stats<<<1, COUT>>>(g2, b2, N, STAT_BLKS);

    bn_relu_out4<<<(total4 + 255) / 256, 256>>>((const float4*)H2p, (float4*)out, total4);
}